// round 1
// baseline (speedup 1.0000x reference)
#include <cuda_runtime.h>

#define DIM 4096
#define THREADS 256
#define RPT 16                      // registers (elements) per thread
#define SPAD(e) ((e) + ((e) >> 4))  // +1 float pad per 16 → conflict-free STS

__global__ __launch_bounds__(THREADS)
void fwht4096_kernel(const float* __restrict__ x, float* __restrict__ out) {
    __shared__ float s[DIM + (DIM >> 4)];  // 4352 floats = 17408 B

    const int row = blockIdx.x;
    const int t = threadIdx.x;
    const float* xrow = x + (size_t)row * DIM;
    float* orow = out + (size_t)row * DIM;

    // ---- load 16 contiguous floats per thread (4 x float4) ----
    float v[RPT];
    {
        const float4* xin = reinterpret_cast<const float4*>(xrow) + t * 4;
        float4 a0 = xin[0], a1 = xin[1], a2 = xin[2], a3 = xin[3];
        v[0]=a0.x;  v[1]=a0.y;  v[2]=a0.z;  v[3]=a0.w;
        v[4]=a1.x;  v[5]=a1.y;  v[6]=a1.z;  v[7]=a1.w;
        v[8]=a2.x;  v[9]=a2.y;  v[10]=a2.z; v[11]=a2.w;
        v[12]=a3.x; v[13]=a3.y; v[14]=a3.z; v[15]=a3.w;
    }

    // ---- stages for element bits 0..3 (in-register) ----
#pragma unroll
    for (int h = 1; h <= 8; h <<= 1) {
#pragma unroll
        for (int k = 0; k < RPT; k++) {
            if (!(k & h)) {
                float a = v[k], b = v[k ^ h];
                v[k]     = a + b;
                v[k ^ h] = a - b;
            }
        }
    }

    // ---- stages for element bits 4..8 (lane bits 0..4, warp shuffle) ----
#pragma unroll
    for (int m = 1; m <= 16; m <<= 1) {
        const bool up = (t & m) != 0;   // m <= 16, so (t&m) == (lane&m)
#pragma unroll
        for (int k = 0; k < RPT; k++) {
            float p = __shfl_xor_sync(0xffffffffu, v[k], m);
            v[k] = up ? (p - v[k]) : (v[k] + p);
        }
    }

    // ---- exchange through padded smem for element bits 9..11 (warp bits) ----
    {
        const int base = t * 17;  // SPAD(t*16 + k) = 17t + k for k<16
#pragma unroll
        for (int k = 0; k < RPT; k++) s[base + k] = v[k];
    }
    __syncthreads();

    // thread t owns chains c0=2t, c1=2t+1; each chain = 8 elems stride 512
    float u0[8], u1[8];
    const int c0 = 2 * t;
    const int c1 = 2 * t + 1;
#pragma unroll
    for (int j = 0; j < 8; j++) {
        int e0 = c0 + j * 512;
        int e1 = c1 + j * 512;
        u0[j] = s[SPAD(e0)];
        u1[j] = s[SPAD(e1)];
    }

    // ---- 3 butterfly stages over the j index (element bits 9,10,11) ----
#pragma unroll
    for (int h = 1; h <= 4; h <<= 1) {
#pragma unroll
        for (int j = 0; j < 8; j++) {
            if (!(j & h)) {
                float a0 = u0[j], b0 = u0[j ^ h];
                u0[j] = a0 + b0;  u0[j ^ h] = a0 - b0;
                float a1 = u1[j], b1 = u1[j ^ h];
                u1[j] = a1 + b1;  u1[j ^ h] = a1 - b1;
            }
        }
    }

    // ---- coalesced float2 stores ----
    float2* o2 = reinterpret_cast<float2*>(orow);
#pragma unroll
    for (int j = 0; j < 8; j++) {
        o2[(c0 + j * 512) >> 1] = make_float2(u0[j], u1[j]);
    }
}

extern "C" void kernel_launch(void* const* d_in, const int* in_sizes, int n_in,
                              void* d_out, int out_size) {
    // x is the input whose element count matches the output (8192*4096);
    // H (4096*4096) is implicit in the transform and never touched.
    const float* x = (const float*)d_in[0];
    for (int i = 0; i < n_in; i++) {
        if (in_sizes[i] == out_size) { x = (const float*)d_in[i]; break; }
    }
    float* out = (float*)d_out;
    const int n_rows = out_size / DIM;  // 8192
    fwht4096_kernel<<<n_rows, THREADS>>>(x, out);
}

// round 2
// speedup vs baseline: 1.2852x; 1.2852x over previous
#include <cuda_runtime.h>

#define DIM 4096
#define THREADS 128   // one row per CTA, 4 warps

// padded smem address for element e: +4 words per 128 elements
// (makes both the 128-stride scalar access pattern and the stride-4 vector
//  pattern bank-conflict-free; verified per-instruction above)
#define SADDR(e) ((e) + 4 * ((e) >> 7))

__device__ __forceinline__ void bfly(float& a, float& b) {
    float s = a + b;
    float d = a - b;
    a = s; b = d;
}

__global__ __launch_bounds__(THREADS)
void fwht4096_noshfl_kernel(const float* __restrict__ x, float* __restrict__ out) {
    __shared__ float s[DIM + 4 * (DIM >> 7)];  // 4224 floats = 16896 B

    const int row = blockIdx.x;
    const int t = threadIdx.x;

    const float4* __restrict__ xin =
        reinterpret_cast<const float4*>(x + (size_t)row * DIM);
    float4* __restrict__ oq =
        reinterpret_cast<float4*>(out + (size_t)row * DIM);

    // ================= Phase 1 =================
    // ownership: e = k_lo + 4*t + 512*k_hi   (k_lo: e-bits 0-1, k_hi: e-bits 9-11)
    // reg index k = 4*k_hi + k_lo  -> reg bits map to e-bits {0,1,9,10,11}
    float v[32];
#pragma unroll
    for (int kh = 0; kh < 8; kh++) {
        float4 f = xin[t + 128 * kh];   // 512B contiguous per warp instr
        v[4 * kh + 0] = f.x;
        v[4 * kh + 1] = f.y;
        v[4 * kh + 2] = f.z;
        v[4 * kh + 3] = f.w;
    }

    // butterfly e-bits {0,1,9,10,11} == all 5 register-index bits
#pragma unroll
    for (int h = 1; h <= 16; h <<= 1) {
#pragma unroll
        for (int k = 0; k < 32; k++) {
            if (!(k & h)) bfly(v[k], v[k ^ h]);
        }
    }

    // write to smem at canonical padded addresses (float4 stores)
    {
        const int base = 4 * t + 4 * (t >> 5);  // SADDR(4t + 512*kh) = base + 528*kh
#pragma unroll
        for (int kh = 0; kh < 8; kh++) {
            *reinterpret_cast<float4*>(&s[base + 528 * kh]) =
                make_float4(v[4 * kh + 0], v[4 * kh + 1], v[4 * kh + 2], v[4 * kh + 3]);
        }
    }
    __syncthreads();

    // ================= Phase 2 =================
    // ownership: e = k_lo2 + 4*j + 128*m   (j = e-bits 2-6 in registers)
    // k_lo2 = t&3 (e-bits 0-1), m = t>>2 (e-bits 7-11)
    float u[32];
    {
        const int klo2 = t & 3;
        const int m = t >> 2;
        const int base2 = klo2 + 132 * m;  // SADDR(k_lo2 + 128*m) ; +4j stays exact
#pragma unroll
        for (int j = 0; j < 32; j++) u[j] = s[base2 + 4 * j];

        // butterfly e-bits {2,3,4,5,6} == register-index bits of j
#pragma unroll
        for (int h = 1; h <= 16; h <<= 1) {
#pragma unroll
            for (int j = 0; j < 32; j++) {
                if (!(j & h)) bfly(u[j], u[j ^ h]);
            }
        }

        // write back to the SAME canonical addresses (each addr owned by this
        // thread in this phase -> no cross-thread hazard before the barrier)
#pragma unroll
        for (int j = 0; j < 32; j++) s[base2 + 4 * j] = u[j];
    }
    __syncthreads();

    // ================= Phase 3 =================
    // ownership: e = k_lo3 + 4*l + 128*km + 1024*w3
    // reg index = 4*km + k_lo3 -> reg bits map to e-bits {0,1,7,8,9}
    // l = t&31 (e-bits 2-6), w3 = t>>5 (e-bits 10-11)
    float w[32];
    {
        const int l = t & 31;
        const int w3 = t >> 5;
        const int base3 = 4 * l + 1056 * w3;  // SADDR(4l + 1024*w3)
#pragma unroll
        for (int km = 0; km < 8; km++) {
            float4 f = *reinterpret_cast<const float4*>(&s[base3 + 132 * km]);
            w[4 * km + 0] = f.x;
            w[4 * km + 1] = f.y;
            w[4 * km + 2] = f.z;
            w[4 * km + 3] = f.w;
        }

        // remaining bits: e-bits {7,8} == reg-index bits 2,3 (h = 4, 8).
        // reg bits 0,1 (e-bits 0,1) and bit 4 (e-bit 9) were done in phases 1/2.
#pragma unroll
        for (int h = 4; h <= 8; h <<= 1) {
#pragma unroll
            for (int k = 0; k < 32; k++) {
                if (!(k & h)) bfly(w[k], w[k ^ h]);
            }
        }

        // fully coalesced float4 stores: float4 index = l + 32*km + 256*w3
#pragma unroll
        for (int km = 0; km < 8; km++) {
            oq[l + 32 * km + 256 * w3] =
                make_float4(w[4 * km + 0], w[4 * km + 1], w[4 * km + 2], w[4 * km + 3]);
        }
    }
}

extern "C" void kernel_launch(void* const* d_in, const int* in_sizes, int n_in,
                              void* d_out, int out_size) {
    // x is the input whose element count equals out_size (N_TOKENS*DIM);
    // H is implicit in the transform and never read.
    const float* x = (const float*)d_in[0];
    for (int i = 0; i < n_in; i++) {
        if (in_sizes[i] == out_size) { x = (const float*)d_in[i]; break; }
    }
    float* out = (float*)d_out;
    const int n_rows = out_size / DIM;  // 8192
    fwht4096_noshfl_kernel<<<n_rows, THREADS>>>(x, out);
}